// round 8
// baseline (speedup 1.0000x reference)
#include <cuda_runtime.h>
#include <cuda_bf16.h>

// DinoPool == masked average pooling of x over 512-row blocks.
// x: [B=4, S=4096, C=384] fp32 -> out same shape.
//
// R8: pipelined rounds. Grid (12,8,4)=384 CTAs x 256 thr as R6, but each
// CTA processes its 8-float4 column chunk in 4 rounds of 2 columns:
//   read 512x32B -> reduce -> store 512x32B (fire-and-forget)
// so round k's stores drain under round k+1's loads. Chip-wide the L2
// write stream (measured ~3.1TB/s cap => ~8.1us for 25MB) starts ~1.1us
// in and overlaps the DRAM read stream (~4.9us standalone).

static constexpr int S     = 4096;
static constexpr int C     = 384;
static constexpr int C4    = C / 4;    // 96
static constexpr int BLOCK = 512;
static constexpr int NT    = 256;
static constexpr int NRND  = 4;        // rounds of 2 float4 columns

__global__ __launch_bounds__(NT, 8)
void dinopool_kernel(const float* __restrict__ x, float* __restrict__ out) {
    const int chunk = blockIdx.x;   // 0..11  (8 float4 columns)
    const int blk   = blockIdx.y;   // 0..7
    const int bat   = blockIdx.z;   // 0..3

    const int t   = threadIdx.x;
    const int col = t & 1;          // which of the 2 columns this round
    const int rg  = t >> 1;         // 0..127, 4 rows each

    const float4* __restrict__ x4 = reinterpret_cast<const float4*>(x);
    float4* __restrict__ o4       = reinterpret_cast<float4*>(out);

    const size_t rowbase = (size_t)bat * S + (size_t)blk * BLOCK;

    __shared__ float4 wsum[NT / 32][2];   // per-warp, per-col partials
    __shared__ float4 smean[2];

    #pragma unroll
    for (int cp = 0; cp < NRND; cp++) {
        const size_t cbase = (size_t)chunk * 8 + cp * 2;

        // ---- read 4 rows (32B segments, fully coalesced per warp) ----
        const size_t p = (rowbase + (size_t)rg * 4) * C4 + cbase + col;
        float4 a = x4[p];
        float4 b = x4[p + C4];
        float4 c = x4[p + 2 * C4];
        float4 d = x4[p + 3 * C4];
        float4 acc;
        acc.x = (a.x + b.x) + (c.x + d.x);
        acc.y = (a.y + b.y) + (c.y + d.y);
        acc.z = (a.z + b.z) + (c.z + d.z);
        acc.w = (a.w + b.w) + (c.w + d.w);

        // ---- butterfly reduce over the 16 same-col lanes of the warp ----
        #pragma unroll
        for (int off = 16; off >= 2; off >>= 1) {
            acc.x += __shfl_xor_sync(0xffffffffu, acc.x, off);
            acc.y += __shfl_xor_sync(0xffffffffu, acc.y, off);
            acc.z += __shfl_xor_sync(0xffffffffu, acc.z, off);
            acc.w += __shfl_xor_sync(0xffffffffu, acc.w, off);
        }
        if ((t & 31) < 2) wsum[t >> 5][t & 1] = acc;
        __syncthreads();          // also guarantees prior round's stores done

        if (t < 2) {
            float4 m = wsum[0][t];
            #pragma unroll
            for (int w = 1; w < NT / 32; w++) {
                float4 v = wsum[w][t];
                m.x += v.x; m.y += v.y; m.z += v.z; m.w += v.w;
            }
            const float inv = 1.0f / (float)BLOCK;
            m.x *= inv; m.y *= inv; m.z *= inv; m.w *= inv;
            smean[t] = m;
        }
        __syncthreads();

        const float4 m0 = smean[0];
        const float4 m1 = smean[1];

        // ---- write 512 rows x 2 cols (1024 float4), coalesced ----
        #pragma unroll
        for (int i = 0; i < 1024 / NT; i++) {
            const int idx = i * NT + t;         // 0..1023
            const int row = idx >> 1;
            const int cc  = idx & 1;
            o4[(rowbase + row) * C4 + cbase + cc] = cc ? m1 : m0;
        }
        // no trailing sync needed: next round's first sync covers reuse
    }
}

extern "C" void kernel_launch(void* const* d_in, const int* in_sizes, int n_in,
                              void* d_out, int out_size) {
    const float* x = (const float*)d_in[0];   // [4, 4096, 384] fp32
    float* out     = (float*)d_out;
    (void)in_sizes; (void)n_in; (void)out_size;

    dim3 grid(12, 8, 4);   // 384 CTAs
    dinopool_kernel<<<grid, NT>>>(x, out);
}

// round 9
// speedup vs baseline: 1.0290x; 1.0290x over previous
#include <cuda_runtime.h>
#include <cuda_bf16.h>

// DinoPool == masked average pooling of x over 512-row blocks.
// x: [B=4, S=4096, C=384] fp32 -> out same shape.
//
// R9: warp-autonomous, barrier-free. Each warp owns 2 float4 columns of one
// (bat, blk) group: 32 coalesced loads/lane (lane pairs share a 32B sector),
// shfl_xor butterfly over the 16 row-groups (no smem, no __syncthreads),
// then 32 stores/lane. Warps desync so the store stream overlaps the load
// stream chip-wide; MLP stays at 32 independent loads per lane.
// Grid 384 CTAs x 128 thr = R6's proven full-coverage shape.

static constexpr int S     = 4096;
static constexpr int C     = 384;
static constexpr int C4    = C / 4;    // 96 float4 per row
static constexpr int BLOCK = 512;
static constexpr int NT    = 128;      // 4 warps; warp = 2 float4 cols
static constexpr int RPT   = 32;       // rows per lane (512 / 16 rowgroups)

__global__ __launch_bounds__(NT, 8)
void dinopool_kernel(const float* __restrict__ x, float* __restrict__ out) {
    const int chunk = blockIdx.x;   // 0..11 (8 float4 columns)
    const int blk   = blockIdx.y;   // 0..7
    const int bat   = blockIdx.z;   // 0..3

    const int lane = threadIdx.x & 31;
    const int wid  = threadIdx.x >> 5;          // 0..3
    const int col  = lane & 1;                  // 0..1
    const int rg   = lane >> 1;                 // 0..15, 32 rows each

    const float4* __restrict__ x4 = reinterpret_cast<const float4*>(x);
    float4* __restrict__ o4       = reinterpret_cast<float4*>(out);

    const size_t rowbase = (size_t)bat * S + (size_t)blk * BLOCK;
    const size_t cbase   = (size_t)chunk * 8 + wid * 2;

    // ---- 32 independent loads per lane (16 x 32B full sectors per warp-ld)
    const size_t p0 = (rowbase + (size_t)rg * RPT) * C4 + cbase + col;
    float4 acc = make_float4(0.f, 0.f, 0.f, 0.f);
    #pragma unroll
    for (int r = 0; r < RPT; r++) {
        float4 v = __ldg(&x4[p0 + (size_t)r * C4]);
        acc.x += v.x; acc.y += v.y; acc.z += v.z; acc.w += v.w;
    }

    // ---- butterfly over the 16 rowgroups (col parity preserved) ----
    #pragma unroll
    for (int off = 16; off >= 2; off >>= 1) {
        acc.x += __shfl_xor_sync(0xffffffffu, acc.x, off);
        acc.y += __shfl_xor_sync(0xffffffffu, acc.y, off);
        acc.z += __shfl_xor_sync(0xffffffffu, acc.z, off);
        acc.w += __shfl_xor_sync(0xffffffffu, acc.w, off);
    }
    const float inv = 1.0f / (float)BLOCK;
    acc.x *= inv; acc.y *= inv; acc.z *= inv; acc.w *= inv;
    // every lane now holds the mean for its column parity (lane&1)

    // ---- 32 stores per lane: 512 rows x 2 cols, coalesced ----
    // idx = i*32 + lane; row = idx>>1; col = idx&1 == lane&1 (stride 32 even)
    #pragma unroll
    for (int i = 0; i < RPT; i++) {
        const int idx = i * 32 + lane;
        const int row = idx >> 1;
        o4[(rowbase + row) * C4 + cbase + col] = acc;
    }
}

extern "C" void kernel_launch(void* const* d_in, const int* in_sizes, int n_in,
                              void* d_out, int out_size) {
    const float* x = (const float*)d_in[0];   // [4, 4096, 384] fp32
    float* out     = (float*)d_out;
    (void)in_sizes; (void)n_in; (void)out_size;

    dim3 grid(12, 8, 4);   // 384 CTAs x 128 thr
    dinopool_kernel<<<grid, NT>>>(x, out);
}

// round 10
// speedup vs baseline: 1.1351x; 1.1032x over previous
#include <cuda_runtime.h>
#include <cuda_bf16.h>

// DinoPool == masked average pooling of x over 512-row blocks.
// x: [B=4, S=4096, C=384] fp32 -> out same shape.
//
// R10: fine-grained load balance. 1536 CTAs x 64 thr; unit = (bat, blk,
// 2-float4-col chunk). 10.4 CTAs/SM (ceil 11 -> ~6% imbalance vs R6's 16%),
// 20.8 warps/SM, 16 independent loads/thread (MLP preserved).
// Warp butterfly + one 2-warp smem exchange; stores 512B-contiguous/warp.

static constexpr int S     = 4096;
static constexpr int C     = 384;
static constexpr int C4    = C / 4;    // 96 float4 per row
static constexpr int BLOCK = 512;
static constexpr int NT    = 64;       // 2 warps
static constexpr int NCH   = C4 / 2;   // 48 chunks of 2 float4 cols
static constexpr int RPT   = 16;       // rows per thread (512 / 32 rowgroups)

__global__ __launch_bounds__(NT, 16)
void dinopool_kernel(const float* __restrict__ x, float* __restrict__ out) {
    const int chunk = blockIdx.x;   // 0..47
    const int blk   = blockIdx.y;   // 0..7
    const int bat   = blockIdx.z;   // 0..3

    const int t    = threadIdx.x;        // 0..63
    const int col  = t & 1;              // float4 col parity
    const int rg   = t >> 1;             // 0..31, 16 rows each
    const int wid  = t >> 5;             // 0..1

    const float4* __restrict__ x4 = reinterpret_cast<const float4*>(x);
    float4* __restrict__ o4       = reinterpret_cast<float4*>(out);

    const size_t rowbase = (size_t)bat * S + (size_t)blk * BLOCK;
    const size_t cbase   = (size_t)chunk * 2;

    // ---- 16 independent loads per thread ----
    const size_t p0 = (rowbase + (size_t)rg * RPT) * C4 + cbase + col;
    float4 acc = make_float4(0.f, 0.f, 0.f, 0.f);
    #pragma unroll
    for (int r = 0; r < RPT; r++) {
        float4 v = __ldg(&x4[p0 + (size_t)r * C4]);
        acc.x += v.x; acc.y += v.y; acc.z += v.z; acc.w += v.w;
    }

    // ---- butterfly over the 16 same-parity lanes of each warp ----
    #pragma unroll
    for (int off = 16; off >= 2; off >>= 1) {
        acc.x += __shfl_xor_sync(0xffffffffu, acc.x, off);
        acc.y += __shfl_xor_sync(0xffffffffu, acc.y, off);
        acc.z += __shfl_xor_sync(0xffffffffu, acc.z, off);
        acc.w += __shfl_xor_sync(0xffffffffu, acc.w, off);
    }
    // lanes 0/1 of each warp hold that warp's half-sum per column parity

    __shared__ float4 part[2][2];        // [warp][col]
    if ((t & 31) < 2) part[wid][t & 1] = acc;
    __syncthreads();

    float4 a = part[0][col];
    float4 b = part[1][col];
    const float inv = 1.0f / (float)BLOCK;
    float4 mean;
    mean.x = (a.x + b.x) * inv;
    mean.y = (a.y + b.y) * inv;
    mean.z = (a.z + b.z) * inv;
    mean.w = (a.w + b.w) * inv;

    // ---- 16 stores per thread: 512 rows x 2 cols, contiguous per warp ----
    // idx = i*64 + t; row = idx>>1; store col = idx&1 == t&1 (64 even)
    #pragma unroll
    for (int i = 0; i < RPT; i++) {
        const int row = (i * NT + t) >> 1;
        o4[(rowbase + row) * C4 + cbase + col] = mean;
    }
}

extern "C" void kernel_launch(void* const* d_in, const int* in_sizes, int n_in,
                              void* d_out, int out_size) {
    const float* x = (const float*)d_in[0];   // [4, 4096, 384] fp32
    float* out     = (float*)d_out;
    (void)in_sizes; (void)n_in; (void)out_size;

    dim3 grid(NCH /*48*/, 8, 4);   // 1536 CTAs x 64 thr
    dinopool_kernel<<<grid, NT>>>(x, out);
}